// round 8
// baseline (speedup 1.0000x reference)
#include <cuda_runtime.h>

#define H 32
#define WPB 7           // warps per block; each warp = 2 batch rows
#define THREADS (WPB*32)
#define CHUNK 16        // deferred-output chunk
#define RSTR2 68        // dup-ring: row B offset in floats (272B -> disjoint banks)
#define TSTRIDE 560     // hT: row B offset (floats), 560%32==16 -> 16-bank shift

typedef unsigned long long ull;

// ---------- packed f32x2 helpers (sm_103a dual FP32 pipe) ----------
__device__ __forceinline__ ull ffma2(ull a, ull b, ull c) {
    ull d;
    asm("fma.rn.f32x2 %0, %1, %2, %3;" : "=l"(d) : "l"(a), "l"(b), "l"(c));
    return d;
}
__device__ __forceinline__ ull subf2(ull a, ull b) {
    ull d;
    asm("sub.rn.f32x2 %0, %1, %2;" : "=l"(d) : "l"(a), "l"(b));
    return d;
}
__device__ __forceinline__ ull pack2(float lo, float hi) {
    ull d;
    asm("mov.b64 %0, {%1, %2};" : "=l"(d) : "f"(lo), "f"(hi));
    return d;
}
__device__ __forceinline__ void unpack2(ull a, float& lo, float& hi) {
    asm("mov.b64 {%0, %1}, %2;" : "=f"(lo), "=f"(hi) : "l"(a));
}
__device__ __forceinline__ float tanh_ap(float x) {
    float r; asm("tanh.approx.f32 %0, %1;" : "=f"(r) : "f"(x)); return r;
}
__device__ __forceinline__ ull tanh2(ull a) {
    float lo, hi; unpack2(a, lo, hi);
    return pack2(tanh_ap(lo), tanh_ap(hi));
}

// One warp = 2 batch rows (half-warp per row); lane owns units (u0, u0+16) of
// its row, processed as ONE f32x2 lane pair: weights packed (W[u0][k],W[u1][k]),
// h broadcast duplicated so accumulators ARE the packed gate pre-activations.
// grid=147 x 7 warps = 1024 row-pairs, single wave, all SMs.
__global__ void __launch_bounds__(THREADS, 1)
gru_warp_kernel(const float* __restrict__ x,     // [B,T]
                const float* __restrict__ h0,    // [B,H]
                const float* __restrict__ W_ih,  // [3H] (I=1)
                const float* __restrict__ W_hh,  // [3H,H]
                const float* __restrict__ b_ih,  // [3H]
                const float* __restrict__ b_hh,  // [3H]
                const float* __restrict__ W_out, // [H]
                const float* __restrict__ b_out, // [1]
                float* __restrict__ y,           // [B,T]
                float* __restrict__ hn,          // [B,H]
                int B, int T)
{
    __shared__ __align__(16) float ring[WPB][2][2 * RSTR2]; // dup-pair h, 2 rows, dbl-buf
    __shared__ float hT[WPB][2][TSTRIDE];                   // per-row 32x17 history
    __shared__ float wout_s[H + 1];                         // [32]=b_out

    const int lane = threadIdx.x & 31;
    const int w    = threadIdx.x >> 5;
    const int npairs = B >> 1;
    const int p    = blockIdx.x * WPB + w;

    if (threadIdx.x < H) wout_s[threadIdx.x] = W_out[threadIdx.x];
    if (threadIdx.x == H) wout_s[H] = b_out[0];
    __syncthreads();
    if (p >= npairs) return;

    const int u0  = lane & 15;     // first hidden unit this lane owns
    const int r   = lane >> 4;     // which row of the pair this half-warp runs
    const int row = 2 * p + r;     // global batch row
    const int u1  = u0 + 16;

    // ---- weights packed ACROSS UNITS: Wg2[k] = (Wg[u0][k], Wg[u1][k]).
    //      r/z pre-scaled by 0.5: sigmoid(a) = 0.5 + 0.5*tanh(a/2). ----
    ull Wr2[32], Wz2[32], Wn2[32];
    {
        const float* wr0 = W_hh + (size_t)u0 * H;
        const float* wz0 = W_hh + (size_t)(H + u0) * H;
        const float* wn0 = W_hh + (size_t)(2 * H + u0) * H;
        const float* wr1 = W_hh + (size_t)u1 * H;
        const float* wz1 = W_hh + (size_t)(H + u1) * H;
        const float* wn1 = W_hh + (size_t)(2 * H + u1) * H;
        #pragma unroll
        for (int k = 0; k < 32; k++) {
            Wr2[k] = pack2(0.5f * wr0[k], 0.5f * wr1[k]);
            Wz2[k] = pack2(0.5f * wz0[k], 0.5f * wz1[k]);
            Wn2[k] = pack2(wn0[k], wn1[k]);
        }
    }
    const ull wihr2 = pack2(0.5f * W_ih[u0],    0.5f * W_ih[u1]);
    const ull wihz2 = pack2(0.5f * W_ih[H + u0], 0.5f * W_ih[H + u1]);
    const ull wihn2 = pack2(W_ih[2 * H + u0],   W_ih[2 * H + u1]);
    // gate biases folded into packed accumulator inits
    const ull ir2 = pack2(0.5f * (b_ih[u0] + b_hh[u0]),
                          0.5f * (b_ih[u1] + b_hh[u1]));
    const ull iz2 = pack2(0.5f * (b_ih[H + u0] + b_hh[H + u0]),
                          0.5f * (b_ih[H + u1] + b_hh[H + u1]));
    const ull in2 = pack2(b_hh[2 * H + u0], b_hh[2 * H + u1]); // n hidden bias
    const ull bin2 = pack2(b_ih[2 * H + u0], b_ih[2 * H + u1]);
    const ull HALF2 = 0x3F0000003F000000ull;                   // (0.5f, 0.5f)

    ull h2 = pack2(h0[(size_t)row * H + u0], h0[(size_t)row * H + u1]);
    {   // seed dup-ring parity 1 (read by step 0)
        float hA, hB; unpack2(h2, hA, hB);
        ull* rg = (ull*)&ring[w][1][r * RSTR2];
        rg[u0] = pack2(hA, hA);
        rg[u1] = pack2(hB, hB);
    }
    __syncwarp();

    const float* xrow = x + (size_t)row * T;
    float*       yrow = y + (size_t)row * T;
    float* hTrow = &hT[w][r][0];

    for (int t0 = 0; t0 < T; t0 += CHUNK) {
        const float xv = xrow[t0 + u0];   // lane u0==t stages this row's inputs

        #pragma unroll 2
        for (int s = 0; s < CHUNK; s++) {
            const int rd = (s & 1) ^ 1;
            const int wb = (s & 1);

            const float xt = __shfl_sync(0xffffffffu, xv, s, 16); // per-half bcast
            const ull xt2 = pack2(xt, xt);

            // dup-pairs: hp[i] = (h[2i],h[2i], h[2i+1],h[2i+1])
            const ulonglong2* hp = (const ulonglong2*)&ring[w][rd][r * RSTR2];

            ull ar = ir2, az = iz2, an = in2;   // accumulators ARE packed gates
            #pragma unroll
            for (int q = 0; q < 16; q++) {
                const ulonglong2 hv = hp[q];    // (h_k,h_k),(h_{k+1},h_{k+1})
                ar = ffma2(hv.x, Wr2[2 * q],     ar);
                az = ffma2(hv.x, Wz2[2 * q],     az);
                an = ffma2(hv.x, Wn2[2 * q],     an);
                ar = ffma2(hv.y, Wr2[2 * q + 1], ar);
                az = ffma2(hv.y, Wz2[2 * q + 1], az);
                an = ffma2(hv.y, Wn2[2 * q + 1], an);
            }
            // packed epilogue: both units at once
            const ull rg2 = ffma2(HALF2, tanh2(ffma2(xt2, wihr2, ar)), HALF2);
            const ull zg2 = ffma2(HALF2, tanh2(ffma2(xt2, wihz2, az)), HALF2);
            const ull ng2 = tanh2(ffma2(rg2, an, ffma2(xt2, wihn2, bin2)));
            h2 = ffma2(zg2, subf2(h2, ng2), ng2);   // (1-z)*n + z*h

            float hA, hB; unpack2(h2, hA, hB);
            ull* rgw = (ull*)&ring[w][wb][r * RSTR2];
            rgw[u0] = pack2(hA, hA);          // dup-pair broadcast store
            rgw[u1] = pack2(hB, hB);
            hTrow[17 * u0 + s] = hA;          // history for deferred y
            hTrow[17 * u1 + s] = hB;
            __syncwarp();
        }

        // Deferred y: every lane produces one output (row r, timestep u0).
        float acc = 0.0f;
        #pragma unroll
        for (int j = 0; j < H; j++)
            acc = fmaf(hTrow[17 * j + u0], wout_s[j], acc);
        yrow[t0 + u0] = acc + wout_s[H];      // 2x64B coalesced, all lanes
        __syncwarp();                          // hT WAR before next chunk
    }

    {
        float hA, hB; unpack2(h2, hA, hB);
        hn[(size_t)row * H + u0] = hA;
        hn[(size_t)row * H + u1] = hB;
    }
}

extern "C" void kernel_launch(void* const* d_in, const int* in_sizes, int n_in,
                              void* d_out, int out_size) {
    const float* x     = (const float*)d_in[0];   // [B,T,1]
    const float* h0    = (const float*)d_in[1];   // [1,B,H]
    const float* W_ih  = (const float*)d_in[2];   // [3H,1]
    const float* W_hh  = (const float*)d_in[3];   // [3H,H]
    const float* b_ih  = (const float*)d_in[4];   // [3H]
    const float* b_hh  = (const float*)d_in[5];   // [3H]
    const float* W_out = (const float*)d_in[6];   // [1,H]
    const float* b_out = (const float*)d_in[7];   // [1]
    float* out = (float*)d_out;

    const int B = in_sizes[1] / H;                // 2048
    const int T = in_sizes[0] / B;                // 1024

    float* y  = out;                              // [B,T]
    float* hn = out + (size_t)B * T;              // [B,H]

    const int npairs = B / 2;                     // 1024
    const int grid = (npairs + WPB - 1) / WPB;    // 147 -> all SMs, single wave
    gru_warp_kernel<<<grid, THREADS>>>(x, h0, W_ih, W_hh, b_ih, b_hh,
                                       W_out, b_out, y, hn, B, T);
}